// round 16
// baseline (speedup 1.0000x reference)
#include <cuda_runtime.h>
#include <cuda_fp16.h>
#include <cstdint>

constexpr int B_ = 8, N_ = 1024, C_ = 256, H_ = 4, D_ = 64;
constexpr int M_ = B_ * N_;

__device__ __half g_Wxh[M_ * C_];    // fp16 Wx [row][256]
__device__ float  g_eiT[H_ * M_];    // transposed: [h][row]
__device__ float  g_ejT[H_ * M_];

// ---------------------------------------------------------------------------
__device__ __forceinline__ void cpasync16(uint32_t dst, const void* src) {
    asm volatile("cp.async.ca.shared.global [%0], [%1], 16;\n" :: "r"(dst), "l"(src));
}
__device__ __forceinline__ uint32_t smem_u32(const void* p) {
    return (uint32_t)__cvta_generic_to_shared(p);
}
__device__ __forceinline__ void ldsm_x4(uint32_t& r0, uint32_t& r1, uint32_t& r2,
                                        uint32_t& r3, uint32_t a) {
    asm volatile("ldmatrix.sync.aligned.m8n8.x4.shared.b16 {%0,%1,%2,%3},[%4];"
                 : "=r"(r0), "=r"(r1), "=r"(r2), "=r"(r3) : "r"(a));
}
__device__ __forceinline__ void ldsm_x4t(uint32_t& r0, uint32_t& r1, uint32_t& r2,
                                         uint32_t& r3, uint32_t a) {
    asm volatile("ldmatrix.sync.aligned.m8n8.x4.trans.shared.b16 {%0,%1,%2,%3},[%4];"
                 : "=r"(r0), "=r"(r1), "=r"(r2), "=r"(r3) : "r"(a));
}
__device__ __forceinline__ void mma_f16(float* c, const uint32_t* a,
                                        uint32_t b0, uint32_t b1) {
    asm volatile(
        "mma.sync.aligned.m16n8k16.row.col.f32.f16.f16.f32 "
        "{%0,%1,%2,%3},{%4,%5,%6,%7},{%8,%9},{%0,%1,%2,%3};"
        : "+f"(c[0]), "+f"(c[1]), "+f"(c[2]), "+f"(c[3])
        : "r"(a[0]), "r"(a[1]), "r"(a[2]), "r"(a[3]), "r"(b0), "r"(b1));
}

// ---------------------------------------------------------------------------
// Kernel A: Wx = x @ W via tf32 mma, cp.async 4-stage (unchanged from R13
// except e_i/e_j written transposed [h][row]).
// ---------------------------------------------------------------------------
constexpr int AST = 20;
constexpr int BST = 72;
constexpr int NKT = C_ / 16;

__global__ __launch_bounds__(256, 2) void gemm_tf32_kernel(
    const float* __restrict__ x, const float* __restrict__ W,
    const float* __restrict__ av) {
    __shared__ float As[4][128][AST];
    __shared__ float Bs[4][16][BST];
    __shared__ float s_er[128][2][2];

    const int tid  = threadIdx.x;
    const int lane = tid & 31, warp = tid >> 5;
    const int wm = (warp >> 1) * 32, wn = (warp & 1) * 32;
    const int m0 = blockIdx.y * 128;
    const int h  = blockIdx.x;
    const int n0 = h * 64;
    const int g  = lane >> 2, tg = lane & 3;

    float c[2][4][4] = {};

    const int ar = tid >> 2, aseg = tid & 3;
    const int br = tid >> 4, bseg = tid & 15;

    uint32_t sa  = smem_u32(&As[0][0][0]);
    uint32_t sb_ = smem_u32(&Bs[0][0][0]);
    const uint32_t a_stage = 128 * AST * 4;
    const uint32_t b_stage = 16 * BST * 4;

    auto issue = [&](int kt, int s) {
        const int k0 = kt * 16;
        const float* ga = x + (size_t)(m0 + ar) * C_ + k0 + aseg * 4;
        cpasync16(sa + s * a_stage + ar * (AST * 4) + aseg * 16, ga);
        cpasync16(sa + s * a_stage + (ar + 64) * (AST * 4) + aseg * 16, ga + 64 * C_);
        const float* gb = W + (size_t)(k0 + br) * C_ + n0 + bseg * 4;
        cpasync16(sb_ + s * b_stage + br * (BST * 4) + bseg * 16, gb);
    };

    issue(0, 0);
    asm volatile("cp.async.commit_group;\n" ::: "memory");
    issue(1, 1);
    asm volatile("cp.async.commit_group;\n" ::: "memory");
    issue(2, 2);
    asm volatile("cp.async.commit_group;\n" ::: "memory");

    for (int kt = 0; kt < NKT; kt++) {
        asm volatile("cp.async.wait_group 2;\n" ::: "memory");
        __syncthreads();
        const int st = kt & 3;

        #pragma unroll
        for (int ks = 0; ks < 16; ks += 8) {
            uint32_t a[2][4], b[4][2];
            #pragma unroll
            for (int mf = 0; mf < 2; mf++) {
                const int mb = wm + mf * 16;
                a[mf][0] = __float_as_uint(As[st][mb + g     ][ks + tg]);
                a[mf][1] = __float_as_uint(As[st][mb + g + 8 ][ks + tg]);
                a[mf][2] = __float_as_uint(As[st][mb + g     ][ks + tg + 4]);
                a[mf][3] = __float_as_uint(As[st][mb + g + 8 ][ks + tg + 4]);
            }
            #pragma unroll
            for (int nf = 0; nf < 4; nf++) {
                const int nb = wn + nf * 8 + g;
                b[nf][0] = __float_as_uint(Bs[st][ks + tg    ][nb]);
                b[nf][1] = __float_as_uint(Bs[st][ks + tg + 4][nb]);
            }
            #pragma unroll
            for (int mf = 0; mf < 2; mf++)
                #pragma unroll
                for (int nf = 0; nf < 4; nf++) {
                    asm volatile(
                        "mma.sync.aligned.m16n8k8.row.col.f32.tf32.tf32.f32 "
                        "{%0,%1,%2,%3}, {%4,%5,%6,%7}, {%8,%9}, {%0,%1,%2,%3};"
                        : "+f"(c[mf][nf][0]), "+f"(c[mf][nf][1]),
                          "+f"(c[mf][nf][2]), "+f"(c[mf][nf][3])
                        : "r"(a[mf][0]), "r"(a[mf][1]), "r"(a[mf][2]), "r"(a[mf][3]),
                          "r"(b[nf][0]), "r"(b[nf][1]));
                }
        }

        if (kt + 3 < NKT) issue(kt + 3, (kt + 3) & 3);
        asm volatile("cp.async.commit_group;\n" ::: "memory");
    }

    constexpr float SC = 1.0009765625f;   // 1 + 2^-10 tf32 truncation-bias comp
    #pragma unroll
    for (int mf = 0; mf < 2; mf++)
        #pragma unroll
        for (int nf = 0; nf < 4; nf++)
            #pragma unroll
            for (int k = 0; k < 4; k++) c[mf][nf][k] *= SC;

    float ai[4][2], aj[4][2];
    #pragma unroll
    for (int nf = 0; nf < 4; nf++)
        #pragma unroll
        for (int cc = 0; cc < 2; cc++) {
            const int col = wn + nf * 8 + tg * 2 + cc;
            ai[nf][cc] = av[h * 128 + col];
            aj[nf][cc] = av[h * 128 + 64 + col];
        }

    #pragma unroll
    for (int mf = 0; mf < 2; mf++) {
        float ei0 = 0.f, ei1 = 0.f, ej0 = 0.f, ej1 = 0.f;
        #pragma unroll
        for (int nf = 0; nf < 4; nf++) {
            ei0 += c[mf][nf][0] * ai[nf][0] + c[mf][nf][1] * ai[nf][1];
            ei1 += c[mf][nf][2] * ai[nf][0] + c[mf][nf][3] * ai[nf][1];
            ej0 += c[mf][nf][0] * aj[nf][0] + c[mf][nf][1] * aj[nf][1];
            ej1 += c[mf][nf][2] * aj[nf][0] + c[mf][nf][3] * aj[nf][1];
            const int row = m0 + wm + mf * 16 + g;
            const int col = n0 + wn + nf * 8 + tg * 2;
            *(__half2*)&g_Wxh[(size_t)row * C_ + col] =
                __floats2half2_rn(c[mf][nf][0], c[mf][nf][1]);
            *(__half2*)&g_Wxh[(size_t)(row + 8) * C_ + col] =
                __floats2half2_rn(c[mf][nf][2], c[mf][nf][3]);
        }
        #pragma unroll
        for (int o = 1; o < 4; o <<= 1) {
            ei0 += __shfl_xor_sync(0xffffffffu, ei0, o);
            ei1 += __shfl_xor_sync(0xffffffffu, ei1, o);
            ej0 += __shfl_xor_sync(0xffffffffu, ej0, o);
            ej1 += __shfl_xor_sync(0xffffffffu, ej1, o);
        }
        if (tg == 0) {
            const int r0 = wm + mf * 16 + g;
            s_er[r0][warp & 1][0] = ei0;
            s_er[r0][warp & 1][1] = ej0;
            s_er[r0 + 8][warp & 1][0] = ei1;
            s_er[r0 + 8][warp & 1][1] = ej1;
        }
    }
    __syncthreads();
    if (tid < 128) {
        g_eiT[(size_t)h * M_ + m0 + tid] = s_er[tid][0][0] + s_er[tid][1][0];
        g_ejT[(size_t)h * M_ + m0 + tid] = s_er[tid][0][1] + s_er[tid][1][1];
    }
}

// ---------------------------------------------------------------------------
// Kernel C: dense flash-style attention, fp16 tensor-core PV.
// Block = (rt, h, b): 64 rows x all 1024 j. 256 thr = 8 warps.
// Scores are rank-1 (ei + ej) + adj mask, computed inline; P fp16 in smem;
// Wx chunk cp.async'd; PV via mma.m16n8k16. Softmax shift = per-row bound
// lrelu(ei + max_batch ej) (shift-invariance; no neighbor-max pass).
// ---------------------------------------------------------------------------
constexpr int PST = 72;   // smem row stride in halfs (144B: LDSM conflict-free)

__global__ __launch_bounds__(256, 4) void gat_attn_dense(
    const float* __restrict__ adj, float* __restrict__ out) {
    __shared__ float  s_ej[N_];            // 4 KB
    __shared__ __half s_P[64][PST];        // 9.2 KB
    __shared__ __half s_W[64][PST];        // 9.2 KB
    __shared__ float  s_l[64];
    __shared__ float  s_red[8];

    const int rt = blockIdx.x, h = blockIdx.y, b = blockIdx.z;
    const int tid = threadIdx.x, lane = tid & 31, wid = tid >> 5;
    const int jb = b << 10;
    const int pr = tid >> 2;      // local row 0..63 (P-gen mapping)
    const int jq = tid & 3;       // j quadrant
    const int wm = (wid >> 1) * 16, wn = (wid & 1) * 32;   // mma warp tile

    // ---- stage ej (this head) + block max ----
    {
        float4 v = *(const float4*)(g_ejT + (size_t)h * M_ + jb + tid * 4);
        *(float4*)&s_ej[tid * 4] = v;
        float m = fmaxf(fmaxf(v.x, v.y), fmaxf(v.z, v.w));
        #pragma unroll
        for (int o = 16; o; o >>= 1) m = fmaxf(m, __shfl_xor_sync(0xffffffffu, m, o));
        if (lane == 0) s_red[wid] = m;
    }
    __syncthreads();
    float M = s_red[0];
    #pragma unroll
    for (int w = 1; w < 8; w++) M = fmaxf(M, s_red[w]);

    const float ei_r = g_eiT[(size_t)h * M_ + jb + rt * 64 + pr];
    float mh = ei_r + M; mh = fmaxf(mh, 0.2f * mh);   // >= all scores of row pr

    const float* arow = adj + ((size_t)(jb + rt * 64 + pr) << 10);
    const int jself = pr >> 4, kself = pr & 15;   // self-loop: chunk rt, quad jself

    uint32_t swb = smem_u32(&s_W[0][0]);
    uint32_t spb = smem_u32(&s_P[0][0]);

    float lp = 0.0f;
    float c[4][4] = {};

    for (int ch = 0; ch < 16; ch++) {
        const int jt = ch * 64;

        // ---- stage Wx chunk (64 rows x 64 halfs) via cp.async ----
        #pragma unroll
        for (int it = 0; it < 2; it++) {
            int cc = tid + it * 256;
            int rw = cc >> 3, of = cc & 7;
            const __half* src = g_Wxh + ((size_t)(jb + jt + rw) << 8) + h * 64 + of * 8;
            cpasync16(swb + rw * (PST * 2) + of * 16, src);
        }
        asm volatile("cp.async.commit_group;\n" ::: "memory");

        // ---- P gen: 16 scores for (row pr, j = jt + jq*16 + 0..15) ----
        const bool dochk = (ch == rt) && (jq == jself);
        float4 A4[4], E4[4];
        #pragma unroll
        for (int q = 0; q < 4; q++) {
            A4[q] = *(const float4*)(arow + jt + jq * 16 + q * 4);
            E4[q] = *(const float4*)&s_ej[jt + jq * 16 + q * 4];
        }
        uint32_t hh[8];
        #pragma unroll
        for (int q = 0; q < 4; q++) {
            float av[4] = {A4[q].x, A4[q].y, A4[q].z, A4[q].w};
            float ev[4] = {E4[q].x, E4[q].y, E4[q].z, E4[q].w};
            float pv[4];
            #pragma unroll
            for (int s = 0; s < 4; s++) {
                int k = q * 4 + s;
                float e = ei_r + ev[s];
                e = fmaxf(e, 0.2f * e);              // leaky relu
                bool act = (av[s] != 0.0f) || (dochk && (k == kself));
                e = act ? e - mh : -1e30f;           // mask -> exp = 0
                pv[s] = __expf(e);
                lp += pv[s];
            }
            __half2 p01 = __floats2half2_rn(pv[0], pv[1]);
            __half2 p23 = __floats2half2_rn(pv[2], pv[3]);
            hh[q * 2 + 0] = *(uint32_t*)&p01;
            hh[q * 2 + 1] = *(uint32_t*)&p23;
        }
        *(uint4*)&s_P[pr][jq * 16 + 0] = make_uint4(hh[0], hh[1], hh[2], hh[3]);
        *(uint4*)&s_P[pr][jq * 16 + 8] = make_uint4(hh[4], hh[5], hh[6], hh[7]);

        asm volatile("cp.async.wait_group 0;\n" ::: "memory");
        __syncthreads();

        // ---- PV mma: P (64x64) @ W (64x64) ----
        #pragma unroll
        for (int ks = 0; ks < 4; ks++) {
            uint32_t a[4];
            uint32_t ad = spb + (wm + (lane & 15)) * (PST * 2)
                              + (ks * 16 + ((lane >> 4) << 3)) * 2;
            ldsm_x4(a[0], a[1], a[2], a[3], ad);
            uint32_t b0, b1, b2, b3, b4, b5, b6, b7;
            uint32_t bd = swb + (ks * 16 + (lane & 15)) * (PST * 2)
                              + (wn + ((lane >> 4) << 3)) * 2;
            ldsm_x4t(b0, b1, b2, b3, bd);
            ldsm_x4t(b4, b5, b6, b7, bd + 32);   // +16 halfs
            mma_f16(c[0], a, b0, b1);
            mma_f16(c[1], a, b2, b3);
            mma_f16(c[2], a, b4, b5);
            mma_f16(c[3], a, b6, b7);
        }
        __syncthreads();   // before next chunk overwrites s_P / s_W
    }

    // ---- l: quad reduce, then normalize + store ----
    lp += __shfl_xor_sync(0xffffffffu, lp, 1);
    lp += __shfl_xor_sync(0xffffffffu, lp, 2);
    if (jq == 0) s_l[pr] = lp;
    __syncthreads();

    const int g = lane >> 2, t4 = lane & 3;
    const float inv0 = 1.0f / s_l[wm + g];
    const float inv1 = 1.0f / s_l[wm + g + 8];
    float* o0 = out + ((size_t)(jb + rt * 64 + wm + g)) * C_ + h * 64 + wn;
    float* o1 = o0 + 8 * C_;
    #pragma unroll
    for (int nt = 0; nt < 4; nt++) {
        *(float2*)(o0 + nt * 8 + t4 * 2) = make_float2(c[nt][0] * inv0, c[nt][1] * inv0);
        *(float2*)(o1 + nt * 8 + t4 * 2) = make_float2(c[nt][2] * inv1, c[nt][3] * inv1);
    }
}

// ---------------------------------------------------------------------------
extern "C" void kernel_launch(void* const* d_in, const int* in_sizes, int n_in,
                              void* d_out, int out_size) {
    const float* x   = (const float*)d_in[0];
    const float* adj = (const float*)d_in[1];
    const float* W   = (const float*)d_in[2];
    const float* a   = (const float*)d_in[3];
    float* out = (float*)d_out;

    gemm_tf32_kernel<<<dim3(H_, M_ / 128), 256>>>(x, W, a);
    gat_attn_dense<<<dim3(16, H_, B_), 256>>>(adj, out);
}